// round 3
// baseline (speedup 1.0000x reference)
#include <cuda_runtime.h>
#include <cuda_bf16.h>
#include <cstdint>

// BinaryTimedPSP: out[t] = clip(causal boxcar sum width d, 0, 1).
// Spikes binary => out[t] = 1 iff any spike in [t-d+1, t].
//
// Single-pass segmented scan with decoupled lookback:
//  - T split into SEG=32 segments of 64 steps; per component build a 64-bit
//    spike mask, out_bits = sliding-window-OR(mask, min(d,64)).
//  - Cross-segment influence = "age since last spike" entering the segment;
//    published via a release/acquire scratch table, consumed by successor,
//    which ORs a prefix mask of length min(first_spike, d-1-incoming).
//  - Input read exactly once, output written exactly once. No halo.

#define TDIM    2048
#define SEG     32
#define SEG_LEN 64            // == TDIM/SEG, must be 64 (uint64 masks)
#define BLOCK   128
#define MAXC    8192          // max float4 column-groups (B*N/4)
#define BIGAGE  (1u << 20)

__device__ uint4 g_age[SEG * MAXC];
__device__ unsigned g_flag[SEG * MAXC];

__device__ __forceinline__ unsigned ld_acq(const unsigned* p) {
    unsigned v;
    asm volatile("ld.acquire.gpu.global.b32 %0, [%1];" : "=r"(v) : "l"(p));
    return v;
}
__device__ __forceinline__ void st_rel(unsigned* p, unsigned v) {
    asm volatile("st.release.gpu.global.b32 [%0], %1;" :: "l"(p), "r"(v));
}

// OR of s over a causal window of width d (1 <= d), clamped to 64.
__device__ __forceinline__ unsigned long long window_or(unsigned long long s, unsigned d) {
    unsigned long long r = s;
    unsigned w = 1;
    while (w < d && w < 64u) {
        unsigned sh = d - w;
        if (sh > w) sh = w;
        r |= r << sh;
        w += sh;
    }
    return r;
}

__device__ __forceinline__ unsigned long long prefix_mask(unsigned len) {
    return (len >= 64u) ? ~0ull : ((1ull << len) - 1ull);
}

__global__ __launch_bounds__(BLOCK) void psp_lookback_kernel(
    const float4* __restrict__ x,
    float4* __restrict__ out,
    const int* __restrict__ durp,
    int row4)
{
    const int c = blockIdx.x * BLOCK + threadIdx.x;   // column group
    if (c >= row4) return;
    const int s = blockIdx.y;                          // time segment
    const int t0 = s * SEG_LEN;

    unsigned d = 100;
    if (durp) {
        int dv = *durp;
        if (dv > 0 && dv <= TDIM * 16) d = (unsigned)dv;
    }

    // ---- Phase 1: build spike masks (input read once, high MLP) ----
    unsigned long long m0 = 0, m1 = 0, m2 = 0, m3 = 0;
    const float4* __restrict__ xp = x + (size_t)t0 * row4 + c;
    #pragma unroll 8
    for (int t = 0; t < SEG_LEN; ++t) {
        float4 v = xp[(size_t)t * row4];
        if (v.x != 0.0f) m0 |= 1ull << t;
        if (v.y != 0.0f) m1 |= 1ull << t;
        if (v.z != 0.0f) m2 |= 1ull << t;
        if (v.w != 0.0f) m3 |= 1ull << t;
    }

    // self-resolved final ages (clz of mask) -- valid only if mask != 0
    const int idx = s * MAXC + c;
    bool all_self = (m0 != 0) & (m1 != 0) & (m2 != 0) & (m3 != 0);
    uint4 fin;
    fin.x = (unsigned)__clzll(m0);
    fin.y = (unsigned)__clzll(m1);
    fin.z = (unsigned)__clzll(m2);
    fin.w = (unsigned)__clzll(m3);

    if (all_self) {                    // publish early: unblock successors
        g_age[idx] = fin;
        st_rel(&g_flag[idx], 1u);
    }

    // ---- Phase 2: consume predecessor's resolved incoming age ----
    uint4 inc;
    if (s == 0) {
        inc.x = inc.y = inc.z = inc.w = BIGAGE;
    } else {
        const int pidx = (s - 1) * MAXC + c;
        while (ld_acq(&g_flag[pidx]) == 0u) { __nanosleep(60); }
        inc = g_age[pidx];
    }

    if (!all_self) {                   // resolve spikeless components, publish
        if (m0 == 0) fin.x = inc.x + SEG_LEN;
        if (m1 == 0) fin.y = inc.y + SEG_LEN;
        if (m2 == 0) fin.z = inc.z + SEG_LEN;
        if (m3 == 0) fin.w = inc.w + SEG_LEN;
        g_age[idx] = fin;
        st_rel(&g_flag[idx], 1u);
    }

    // ---- Phase 3: output bits = window-OR + incoming-age prefix ----
    unsigned long long b0 = window_or(m0, d);
    unsigned long long b1 = window_or(m1, d);
    unsigned long long b2 = window_or(m2, d);
    unsigned long long b3 = window_or(m3, d);

    // prefix fix: t < min(first_spike, d-1-incoming) -> 1
    unsigned p0 = (m0 != 0) ? (unsigned)(__ffsll((long long)m0) - 1) : 64u;
    unsigned p1 = (m1 != 0) ? (unsigned)(__ffsll((long long)m1) - 1) : 64u;
    unsigned p2 = (m2 != 0) ? (unsigned)(__ffsll((long long)m2) - 1) : 64u;
    unsigned p3 = (m3 != 0) ? (unsigned)(__ffsll((long long)m3) - 1) : 64u;
    unsigned l0 = (inc.x + 1u < d) ? min(p0, d - 1u - inc.x) : 0u;
    unsigned l1 = (inc.y + 1u < d) ? min(p1, d - 1u - inc.y) : 0u;
    unsigned l2 = (inc.z + 1u < d) ? min(p2, d - 1u - inc.z) : 0u;
    unsigned l3 = (inc.w + 1u < d) ? min(p3, d - 1u - inc.w) : 0u;
    b0 |= prefix_mask(l0);
    b1 |= prefix_mask(l1);
    b2 |= prefix_mask(l2);
    b3 |= prefix_mask(l3);

    // ---- Phase 4: stream out (write once, coalesced) ----
    float4* __restrict__ op = out + (size_t)t0 * row4 + c;
    #pragma unroll 8
    for (int t = 0; t < SEG_LEN; ++t) {
        float4 o;
        o.x = __uint_as_float((unsigned)(-(int)((b0 >> t) & 1ull)) & 0x3F800000u);
        o.y = __uint_as_float((unsigned)(-(int)((b1 >> t) & 1ull)) & 0x3F800000u);
        o.z = __uint_as_float((unsigned)(-(int)((b2 >> t) & 1ull)) & 0x3F800000u);
        o.w = __uint_as_float((unsigned)(-(int)((b3 >> t) & 1ull)) & 0x3F800000u);
        op[(size_t)t * row4] = o;
    }
}

// ---- Fallback (shapes outside scratch capacity): halo scan from R1 ----
__global__ __launch_bounds__(BLOCK) void psp_scan_kernel(
    const float4* __restrict__ x, float4* __restrict__ out,
    const int* __restrict__ durp, int row4, int T, int seg_len)
{
    const int c = blockIdx.x * BLOCK + threadIdx.x;
    if (c >= row4) return;
    int d = 100;
    if (durp) { int dv = *durp; if (dv > 0 && dv <= T * 16) d = dv; }
    const int t0 = blockIdx.y * seg_len;
    int th = t0 - (d - 1); if (th < 0) th = 0;
    int ax = 1 << 28, ay = 1 << 28, az = 1 << 28, aw = 1 << 28;
    for (int t = th; t < t0; ++t) {
        float4 v = x[(size_t)t * row4 + c];
        ax = (v.x != 0.0f) ? 0 : ax + 1; ay = (v.y != 0.0f) ? 0 : ay + 1;
        az = (v.z != 0.0f) ? 0 : az + 1; aw = (v.w != 0.0f) ? 0 : aw + 1;
    }
    int tend = t0 + seg_len; if (tend > T) tend = T;
    for (int t = t0; t < tend; ++t) {
        float4 v = x[(size_t)t * row4 + c];
        ax = (v.x != 0.0f) ? 0 : ax + 1; ay = (v.y != 0.0f) ? 0 : ay + 1;
        az = (v.z != 0.0f) ? 0 : az + 1; aw = (v.w != 0.0f) ? 0 : aw + 1;
        float4 o;
        o.x = (ax < d) ? 1.0f : 0.0f; o.y = (ay < d) ? 1.0f : 0.0f;
        o.z = (az < d) ? 1.0f : 0.0f; o.w = (aw < d) ? 1.0f : 0.0f;
        out[(size_t)t * row4 + c] = o;
    }
}

extern "C" void kernel_launch(void* const* d_in, const int* in_sizes, int n_in,
                              void* d_out, int out_size)
{
    const float* x = (const float*)d_in[0];
    const int* durp = (n_in > 1) ? (const int*)d_in[1] : nullptr;
    float* out = (float*)d_out;

    const int total = in_sizes[0];
    // T is fixed at 2048 for this problem; derive row from it.
    const int T = TDIM;
    const int row = total / T;
    const int row4 = row / 4;

    if ((row % 4 == 0) && (row4 <= MAXC) && (total == T * row)) {
        void* flagp = nullptr;
        cudaGetSymbolAddress(&flagp, g_flag);
        cudaMemsetAsync(flagp, 0, sizeof(unsigned) * SEG * MAXC);
        dim3 grid((row4 + BLOCK - 1) / BLOCK, SEG);
        psp_lookback_kernel<<<grid, BLOCK>>>((const float4*)x, (float4*)out,
                                             durp, row4);
    } else {
        const int seg = 8, seg_len = (T + seg - 1) / seg;
        dim3 grid((row4 + BLOCK - 1) / BLOCK, seg);
        psp_scan_kernel<<<grid, BLOCK>>>((const float4*)x, (float4*)out,
                                         durp, row4, T, seg_len);
    }
}

// round 4
// speedup vs baseline: 1.6511x; 1.6511x over previous
#include <cuda_runtime.h>
#include <cuda_bf16.h>
#include <cstdint>

// BinaryTimedPSP: out[t] = clip(causal boxcar sum width d, 0, 1).
// Binary spikes => out[t] = 1 iff any spike in [t-d+1, t].
//
// Three-pass, synchronization-free:
//   P1 : x -> per-(segment, component) 64-bit spike masks  (256MB read, 8MB write)
//   P2a: masks -> incoming-age table (sequential over 32 segs/col; L2-hot)
//   P2b: masks + ages -> output bits -> float stores        (256MB write)

#define TDIM    2048
#define SEG     32
#define SEG_LEN 64
#define BLOCK   128
#define MAXC    8192          // max float4 column-groups (B*N/4)
#define BIGAGE  (1u << 20)

__device__ ulonglong4 g_mask[SEG * MAXC];   // 8 MiB
__device__ uint4      g_inc [SEG * MAXC];   // 4 MiB  (age entering segment)

// OR of s over causal window width d (clamped to 64). d>=64 -> prefix-OR.
__device__ __forceinline__ unsigned long long window_or(unsigned long long s, unsigned d) {
    unsigned long long r = s;
    unsigned w = 1;
    while (w < d && w < 64u) {
        unsigned sh = d - w;
        if (sh > w) sh = w;
        r |= r << sh;
        w += sh;
    }
    return r;
}
__device__ __forceinline__ unsigned long long prefix_mask(unsigned len) {
    return (len >= 64u) ? ~0ull : ((1ull << len) - 1ull);
}
__device__ __forceinline__ unsigned load_d(const int* durp) {
    unsigned d = 100;
    if (durp) {
        int dv = *durp;
        if (dv > 0 && dv <= TDIM * 16) d = (unsigned)dv;
    }
    return d;
}

// ---- Pass 1: build spike masks ----
__global__ __launch_bounds__(BLOCK) void psp_pass1(
    const float4* __restrict__ x, int row4)
{
    const int c = blockIdx.x * BLOCK + threadIdx.x;
    if (c >= row4) return;
    const int s = blockIdx.y;
    const float4* __restrict__ xp = x + (size_t)(s * SEG_LEN) * row4 + c;

    unsigned long long m0 = 0, m1 = 0, m2 = 0, m3 = 0;
    #pragma unroll 8
    for (int t = 0; t < SEG_LEN; ++t) {
        float4 v = xp[(size_t)t * row4];
        if (v.x != 0.0f) m0 |= 1ull << t;
        if (v.y != 0.0f) m1 |= 1ull << t;
        if (v.z != 0.0f) m2 |= 1ull << t;
        if (v.w != 0.0f) m3 |= 1ull << t;
    }
    ulonglong4 m; m.x = m0; m.y = m1; m.z = m2; m.w = m3;
    g_mask[s * MAXC + c] = m;
}

// ---- Pass 2a: exclusive scan of ages across segments (per column) ----
__global__ __launch_bounds__(BLOCK) void psp_pass2a(int row4)
{
    const int c = blockIdx.x * BLOCK + threadIdx.x;
    if (c >= row4) return;
    uint4 inc; inc.x = inc.y = inc.z = inc.w = BIGAGE;
    #pragma unroll
    for (int s = 0; s < SEG; ++s) {
        g_inc[s * MAXC + c] = inc;
        ulonglong4 m = g_mask[s * MAXC + c];
        inc.x = m.x ? (unsigned)__clzll(m.x) : inc.x + SEG_LEN;
        inc.y = m.y ? (unsigned)__clzll(m.y) : inc.y + SEG_LEN;
        inc.z = m.z ? (unsigned)__clzll(m.z) : inc.z + SEG_LEN;
        inc.w = m.w ? (unsigned)__clzll(m.w) : inc.w + SEG_LEN;
    }
}

// ---- Pass 2b: masks + incoming ages -> output ----
__global__ __launch_bounds__(BLOCK) void psp_pass2b(
    float4* __restrict__ out, const int* __restrict__ durp, int row4)
{
    const int c = blockIdx.x * BLOCK + threadIdx.x;
    if (c >= row4) return;
    const int s = blockIdx.y;
    const unsigned d = load_d(durp);

    ulonglong4 m = g_mask[s * MAXC + c];
    uint4 inc    = g_inc [s * MAXC + c];

    unsigned long long b0 = window_or(m.x, d);
    unsigned long long b1 = window_or(m.y, d);
    unsigned long long b2 = window_or(m.z, d);
    unsigned long long b3 = window_or(m.w, d);

    // prefix fix: bits t < min(first_spike, d-1-inc) forced to 1
    unsigned p0 = m.x ? (unsigned)(__ffsll((long long)m.x) - 1) : 64u;
    unsigned p1 = m.y ? (unsigned)(__ffsll((long long)m.y) - 1) : 64u;
    unsigned p2 = m.z ? (unsigned)(__ffsll((long long)m.z) - 1) : 64u;
    unsigned p3 = m.w ? (unsigned)(__ffsll((long long)m.w) - 1) : 64u;
    unsigned l0 = (inc.x + 1u < d) ? min(p0, d - 1u - inc.x) : 0u;
    unsigned l1 = (inc.y + 1u < d) ? min(p1, d - 1u - inc.y) : 0u;
    unsigned l2 = (inc.z + 1u < d) ? min(p2, d - 1u - inc.z) : 0u;
    unsigned l3 = (inc.w + 1u < d) ? min(p3, d - 1u - inc.w) : 0u;
    b0 |= prefix_mask(l0);
    b1 |= prefix_mask(l1);
    b2 |= prefix_mask(l2);
    b3 |= prefix_mask(l3);

    float4* __restrict__ op = out + (size_t)(s * SEG_LEN) * row4 + c;
    #pragma unroll 8
    for (int t = 0; t < SEG_LEN; ++t) {
        float4 o;
        o.x = __uint_as_float((unsigned)(-(int)((b0 >> t) & 1ull)) & 0x3F800000u);
        o.y = __uint_as_float((unsigned)(-(int)((b1 >> t) & 1ull)) & 0x3F800000u);
        o.z = __uint_as_float((unsigned)(-(int)((b2 >> t) & 1ull)) & 0x3F800000u);
        o.w = __uint_as_float((unsigned)(-(int)((b3 >> t) & 1ull)) & 0x3F800000u);
        op[(size_t)t * row4] = o;
    }
}

// ---- Fallback (odd shapes): R1 halo scan ----
__global__ __launch_bounds__(BLOCK) void psp_scan_kernel(
    const float4* __restrict__ x, float4* __restrict__ out,
    const int* __restrict__ durp, int row4, int T, int seg_len)
{
    const int c = blockIdx.x * BLOCK + threadIdx.x;
    if (c >= row4) return;
    int d = 100;
    if (durp) { int dv = *durp; if (dv > 0 && dv <= T * 16) d = dv; }
    const int t0 = blockIdx.y * seg_len;
    int th = t0 - (d - 1); if (th < 0) th = 0;
    int ax = 1 << 28, ay = 1 << 28, az = 1 << 28, aw = 1 << 28;
    for (int t = th; t < t0; ++t) {
        float4 v = x[(size_t)t * row4 + c];
        ax = (v.x != 0.0f) ? 0 : ax + 1; ay = (v.y != 0.0f) ? 0 : ay + 1;
        az = (v.z != 0.0f) ? 0 : az + 1; aw = (v.w != 0.0f) ? 0 : aw + 1;
    }
    int tend = t0 + seg_len; if (tend > T) tend = T;
    for (int t = t0; t < tend; ++t) {
        float4 v = x[(size_t)t * row4 + c];
        ax = (v.x != 0.0f) ? 0 : ax + 1; ay = (v.y != 0.0f) ? 0 : ay + 1;
        az = (v.z != 0.0f) ? 0 : az + 1; aw = (v.w != 0.0f) ? 0 : aw + 1;
        float4 o;
        o.x = (ax < d) ? 1.0f : 0.0f; o.y = (ay < d) ? 1.0f : 0.0f;
        o.z = (az < d) ? 1.0f : 0.0f; o.w = (aw < d) ? 1.0f : 0.0f;
        out[(size_t)t * row4 + c] = o;
    }
}

extern "C" void kernel_launch(void* const* d_in, const int* in_sizes, int n_in,
                              void* d_out, int out_size)
{
    const float* x = (const float*)d_in[0];
    const int* durp = (n_in > 1) ? (const int*)d_in[1] : nullptr;
    float* out = (float*)d_out;

    const int total = in_sizes[0];
    const int T = TDIM;
    const int row = total / T;
    const int row4 = row / 4;

    if ((row % 4 == 0) && (row4 <= MAXC) && (total == T * row)) {
        const int gx = (row4 + BLOCK - 1) / BLOCK;
        psp_pass1 <<<dim3(gx, SEG), BLOCK>>>((const float4*)x, row4);
        psp_pass2a<<<gx, BLOCK>>>(row4);
        psp_pass2b<<<dim3(gx, SEG), BLOCK>>>((float4*)out, durp, row4);
    } else {
        const int seg = 8, seg_len = (T + seg - 1) / seg;
        dim3 grid((row4 + BLOCK - 1) / BLOCK, seg);
        psp_scan_kernel<<<grid, BLOCK>>>((const float4*)x, (float4*)out,
                                         durp, row4, T, seg_len);
    }
}

// round 5
// speedup vs baseline: 1.9470x; 1.1793x over previous
#include <cuda_runtime.h>
#include <cuda_bf16.h>
#include <cstdint>

// BinaryTimedPSP: out[t] = clip(causal boxcar sum width d, 0, 1).
// Binary spikes => out[t] = 1 iff any spike in [t-d+1, t].
//
// Two-pass, synchronization-free:
//   P1: x -> per-(segment, component) 64-bit spike masks (256MB read, 8MB write)
//   P2: masks (+ bounded lookback over predecessor masks, L2-hot)
//       -> output bits -> float stores (256MB write)

#define TDIM    2048
#define SEG     32
#define SEG_LEN 64
#define BLOCK   128
#define MAXC    8192          // max float4 column-groups (B*N/4)
#define BIGAGE  (1u << 20)

__device__ ulonglong4 g_mask[SEG * MAXC];   // 8 MiB

// OR of s over causal window width d (clamped to 64). d>=64 -> prefix-OR.
__device__ __forceinline__ unsigned long long window_or(unsigned long long s, unsigned d) {
    unsigned long long r = s;
    unsigned w = 1;
    while (w < d && w < 64u) {
        unsigned sh = d - w;
        if (sh > w) sh = w;
        r |= r << sh;
        w += sh;
    }
    return r;
}
__device__ __forceinline__ unsigned long long prefix_mask(unsigned len) {
    return (len >= 64u) ? ~0ull : ((1ull << len) - 1ull);
}
__device__ __forceinline__ unsigned load_d(const int* durp) {
    unsigned d = 100;
    if (durp) {
        int dv = *durp;
        if (dv > 0 && dv <= TDIM * 16) d = (unsigned)dv;
    }
    return d;
}

// ---- Pass 1: build spike masks (unroll 16, split OR chains for MLP) ----
__global__ __launch_bounds__(BLOCK) void psp_pass1(
    const float4* __restrict__ x, int row4)
{
    const int c = blockIdx.x * BLOCK + threadIdx.x;
    if (c >= row4) return;
    const int s = blockIdx.y;
    const float4* __restrict__ xp = x + (size_t)(s * SEG_LEN) * row4 + c;

    unsigned long long m0 = 0, m1 = 0, m2 = 0, m3 = 0;
    #pragma unroll
    for (int tb = 0; tb < SEG_LEN; tb += 16) {
        unsigned long long a0 = 0, a1 = 0, a2 = 0, a3 = 0;   // fresh chains
        #pragma unroll
        for (int k = 0; k < 16; ++k) {
            float4 v = xp[(size_t)(tb + k) * row4];
            if (v.x != 0.0f) a0 |= 1ull << (tb + k);
            if (v.y != 0.0f) a1 |= 1ull << (tb + k);
            if (v.z != 0.0f) a2 |= 1ull << (tb + k);
            if (v.w != 0.0f) a3 |= 1ull << (tb + k);
        }
        m0 |= a0; m1 |= a1; m2 |= a2; m3 |= a3;
    }
    ulonglong4 m; m.x = m0; m.y = m1; m.z = m2; m.w = m3;
    g_mask[s * MAXC + c] = m;
}

// ---- Pass 2: bounded lookback + window-OR + stores ----
__global__ __launch_bounds__(BLOCK) void psp_pass2(
    float4* __restrict__ out, const int* __restrict__ durp, int row4)
{
    const int c = blockIdx.x * BLOCK + threadIdx.x;
    if (c >= row4) return;
    const int s = blockIdx.y;
    const unsigned d = load_d(durp);

    ulonglong4 m = g_mask[s * MAXC + c];

    // incoming age entering this segment: scan predecessors until resolved
    // or until their influence (base >= d-1) vanishes.
    uint4 inc; inc.x = inc.y = inc.z = inc.w = BIGAGE;
    unsigned base = 0;
    for (int j = s - 1; j >= 0 && base + 1u < d; --j) {
        ulonglong4 pm = g_mask[j * MAXC + c];
        if (inc.x == BIGAGE && pm.x) inc.x = base + (unsigned)__clzll(pm.x);
        if (inc.y == BIGAGE && pm.y) inc.y = base + (unsigned)__clzll(pm.y);
        if (inc.z == BIGAGE && pm.z) inc.z = base + (unsigned)__clzll(pm.z);
        if (inc.w == BIGAGE && pm.w) inc.w = base + (unsigned)__clzll(pm.w);
        base += SEG_LEN;
        if (inc.x != BIGAGE && inc.y != BIGAGE && inc.z != BIGAGE && inc.w != BIGAGE)
            break;
    }

    unsigned long long b0 = window_or(m.x, d);
    unsigned long long b1 = window_or(m.y, d);
    unsigned long long b2 = window_or(m.z, d);
    unsigned long long b3 = window_or(m.w, d);

    // prefix fix: bits t < min(first_spike, d-1-inc) forced to 1
    unsigned p0 = m.x ? (unsigned)(__ffsll((long long)m.x) - 1) : 64u;
    unsigned p1 = m.y ? (unsigned)(__ffsll((long long)m.y) - 1) : 64u;
    unsigned p2 = m.z ? (unsigned)(__ffsll((long long)m.z) - 1) : 64u;
    unsigned p3 = m.w ? (unsigned)(__ffsll((long long)m.w) - 1) : 64u;
    unsigned l0 = (inc.x + 1u < d) ? min(p0, d - 1u - inc.x) : 0u;
    unsigned l1 = (inc.y + 1u < d) ? min(p1, d - 1u - inc.y) : 0u;
    unsigned l2 = (inc.z + 1u < d) ? min(p2, d - 1u - inc.z) : 0u;
    unsigned l3 = (inc.w + 1u < d) ? min(p3, d - 1u - inc.w) : 0u;
    b0 |= prefix_mask(l0);
    b1 |= prefix_mask(l1);
    b2 |= prefix_mask(l2);
    b3 |= prefix_mask(l3);

    float4* __restrict__ op = out + (size_t)(s * SEG_LEN) * row4 + c;
    #pragma unroll
    for (int tb = 0; tb < SEG_LEN; tb += 16) {
        #pragma unroll
        for (int k = 0; k < 16; ++k) {
            const int t = tb + k;
            float4 o;
            o.x = __uint_as_float((unsigned)(-(int)((b0 >> t) & 1ull)) & 0x3F800000u);
            o.y = __uint_as_float((unsigned)(-(int)((b1 >> t) & 1ull)) & 0x3F800000u);
            o.z = __uint_as_float((unsigned)(-(int)((b2 >> t) & 1ull)) & 0x3F800000u);
            o.w = __uint_as_float((unsigned)(-(int)((b3 >> t) & 1ull)) & 0x3F800000u);
            op[(size_t)t * row4] = o;
        }
    }
}

// ---- Fallback (odd shapes): halo scan ----
__global__ __launch_bounds__(BLOCK) void psp_scan_kernel(
    const float4* __restrict__ x, float4* __restrict__ out,
    const int* __restrict__ durp, int row4, int T, int seg_len)
{
    const int c = blockIdx.x * BLOCK + threadIdx.x;
    if (c >= row4) return;
    int d = 100;
    if (durp) { int dv = *durp; if (dv > 0 && dv <= T * 16) d = dv; }
    const int t0 = blockIdx.y * seg_len;
    int th = t0 - (d - 1); if (th < 0) th = 0;
    int ax = 1 << 28, ay = 1 << 28, az = 1 << 28, aw = 1 << 28;
    for (int t = th; t < t0; ++t) {
        float4 v = x[(size_t)t * row4 + c];
        ax = (v.x != 0.0f) ? 0 : ax + 1; ay = (v.y != 0.0f) ? 0 : ay + 1;
        az = (v.z != 0.0f) ? 0 : az + 1; aw = (v.w != 0.0f) ? 0 : aw + 1;
    }
    int tend = t0 + seg_len; if (tend > T) tend = T;
    for (int t = t0; t < tend; ++t) {
        float4 v = x[(size_t)t * row4 + c];
        ax = (v.x != 0.0f) ? 0 : ax + 1; ay = (v.y != 0.0f) ? 0 : ay + 1;
        az = (v.z != 0.0f) ? 0 : az + 1; aw = (v.w != 0.0f) ? 0 : aw + 1;
        float4 o;
        o.x = (ax < d) ? 1.0f : 0.0f; o.y = (ay < d) ? 1.0f : 0.0f;
        o.z = (az < d) ? 1.0f : 0.0f; o.w = (aw < d) ? 1.0f : 0.0f;
        out[(size_t)t * row4 + c] = o;
    }
}

extern "C" void kernel_launch(void* const* d_in, const int* in_sizes, int n_in,
                              void* d_out, int out_size)
{
    const float* x = (const float*)d_in[0];
    const int* durp = (n_in > 1) ? (const int*)d_in[1] : nullptr;
    float* out = (float*)d_out;

    const int total = in_sizes[0];
    const int T = TDIM;
    const int row = total / T;
    const int row4 = row / 4;

    if ((row % 4 == 0) && (row4 <= MAXC) && (total == T * row)) {
        const int gx = (row4 + BLOCK - 1) / BLOCK;
        psp_pass1<<<dim3(gx, SEG), BLOCK>>>((const float4*)x, row4);
        psp_pass2<<<dim3(gx, SEG), BLOCK>>>((float4*)out, durp, row4);
    } else {
        const int seg = 8, seg_len = (T + seg - 1) / seg;
        dim3 grid((row4 + BLOCK - 1) / BLOCK, seg);
        psp_scan_kernel<<<grid, BLOCK>>>((const float4*)x, (float4*)out,
                                         durp, row4, T, seg_len);
    }
}

// round 6
// speedup vs baseline: 2.0013x; 1.0279x over previous
#include <cuda_runtime.h>
#include <cuda_bf16.h>
#include <cstdint>

// BinaryTimedPSP: out[t] = clip(causal boxcar sum width d, 0, 1).
// Binary spikes => out[t] = 1 iff any spike in [t-d+1, t].
//
// Two-pass, synchronization-free:
//   P1: x -> per-(segment, component) 64-bit spike masks (256MB read, 8MB write)
//       explicit 8-wide load batching for MLP; streaming loads.
//   P2: masks (+ parallel 2-deep lookback, L2-hot) -> output bits -> stores.

#define TDIM    2048
#define SEG     32
#define SEG_LEN 64
#define BLOCK   128
#define MAXC    8192          // max float4 column-groups (B*N/4)
#define BIGAGE  (1u << 20)

__device__ ulonglong4 g_mask[SEG * MAXC];   // 8 MiB

__device__ __forceinline__ unsigned long long window_or(unsigned long long s, unsigned d) {
    unsigned long long r = s;
    unsigned w = 1;
    while (w < d && w < 64u) {
        unsigned sh = d - w;
        if (sh > w) sh = w;
        r |= r << sh;
        w += sh;
    }
    return r;
}
__device__ __forceinline__ unsigned long long prefix_mask(unsigned len) {
    return (len >= 64u) ? ~0ull : ((1ull << len) - 1ull);
}
__device__ __forceinline__ unsigned load_d(const int* durp) {
    unsigned d = 100;
    if (durp) {
        int dv = *durp;
        if (dv > 0 && dv <= TDIM * 16) d = (unsigned)dv;
    }
    return d;
}

// ---- Pass 1: build spike masks (explicit 8-wide batches -> 8 LDGs in flight) ----
__global__ __launch_bounds__(BLOCK) void psp_pass1(
    const float4* __restrict__ x, int row4)
{
    const int c = blockIdx.x * BLOCK + threadIdx.x;
    if (c >= row4) return;
    const int s = blockIdx.y;
    const float4* __restrict__ xp = x + (size_t)(s * SEG_LEN) * row4 + c;

    unsigned long long m0 = 0, m1 = 0, m2 = 0, m3 = 0;
    #pragma unroll
    for (int tb = 0; tb < SEG_LEN; tb += 8) {
        float4 v[8];
        #pragma unroll
        for (int k = 0; k < 8; ++k)
            v[k] = __ldcs(&xp[(size_t)(tb + k) * row4]);
        #pragma unroll
        for (int k = 0; k < 8; ++k) {
            if (v[k].x != 0.0f) m0 |= 1ull << (tb + k);
            if (v[k].y != 0.0f) m1 |= 1ull << (tb + k);
            if (v[k].z != 0.0f) m2 |= 1ull << (tb + k);
            if (v[k].w != 0.0f) m3 |= 1ull << (tb + k);
        }
    }
    ulonglong4 m; m.x = m0; m.y = m1; m.z = m2; m.w = m3;
    g_mask[s * MAXC + c] = m;
}

// ---- Pass 2: parallel bounded lookback + window-OR + streaming stores ----
__global__ __launch_bounds__(BLOCK) void psp_pass2(
    float4* __restrict__ out, const int* __restrict__ durp, int row4)
{
    const int c = blockIdx.x * BLOCK + threadIdx.x;
    if (c >= row4) return;
    const int s = blockIdx.y;
    const unsigned d = load_d(durp);

    // issue all (up to 3) mask loads in parallel: own + 2 predecessors
    ulonglong4 m = g_mask[s * MAXC + c];
    ulonglong4 pm1 = {0, 0, 0, 0}, pm2 = {0, 0, 0, 0};
    if (s >= 1)            pm1 = g_mask[(s - 1) * MAXC + c];
    if (s >= 2 && d > 65u) pm2 = g_mask[(s - 2) * MAXC + c];

    uint4 inc;
    inc.x = pm1.x ? (unsigned)__clzll(pm1.x) : (pm2.x ? 64u + (unsigned)__clzll(pm2.x) : BIGAGE);
    inc.y = pm1.y ? (unsigned)__clzll(pm1.y) : (pm2.y ? 64u + (unsigned)__clzll(pm2.y) : BIGAGE);
    inc.z = pm1.z ? (unsigned)__clzll(pm1.z) : (pm2.z ? 64u + (unsigned)__clzll(pm2.z) : BIGAGE);
    inc.w = pm1.w ? (unsigned)__clzll(pm1.w) : (pm2.w ? 64u + (unsigned)__clzll(pm2.w) : BIGAGE);

    if (d > 129u) {   // rare general case: continue lookback past 2 segments
        unsigned base = 128;
        for (int j = s - 3; j >= 0 && base + 1u < d; --j) {
            if (inc.x != BIGAGE && inc.y != BIGAGE && inc.z != BIGAGE && inc.w != BIGAGE)
                break;
            ulonglong4 pm = g_mask[j * MAXC + c];
            if (inc.x == BIGAGE && pm.x) inc.x = base + (unsigned)__clzll(pm.x);
            if (inc.y == BIGAGE && pm.y) inc.y = base + (unsigned)__clzll(pm.y);
            if (inc.z == BIGAGE && pm.z) inc.z = base + (unsigned)__clzll(pm.z);
            if (inc.w == BIGAGE && pm.w) inc.w = base + (unsigned)__clzll(pm.w);
            base += SEG_LEN;
        }
    }

    unsigned long long b0 = window_or(m.x, d);
    unsigned long long b1 = window_or(m.y, d);
    unsigned long long b2 = window_or(m.z, d);
    unsigned long long b3 = window_or(m.w, d);

    // prefix fix: bits t < min(first_spike, d-1-inc) forced to 1
    unsigned p0 = m.x ? (unsigned)(__ffsll((long long)m.x) - 1) : 64u;
    unsigned p1 = m.y ? (unsigned)(__ffsll((long long)m.y) - 1) : 64u;
    unsigned p2 = m.z ? (unsigned)(__ffsll((long long)m.z) - 1) : 64u;
    unsigned p3 = m.w ? (unsigned)(__ffsll((long long)m.w) - 1) : 64u;
    unsigned l0 = (inc.x + 1u < d) ? min(p0, d - 1u - inc.x) : 0u;
    unsigned l1 = (inc.y + 1u < d) ? min(p1, d - 1u - inc.y) : 0u;
    unsigned l2 = (inc.z + 1u < d) ? min(p2, d - 1u - inc.z) : 0u;
    unsigned l3 = (inc.w + 1u < d) ? min(p3, d - 1u - inc.w) : 0u;
    b0 |= prefix_mask(l0);
    b1 |= prefix_mask(l1);
    b2 |= prefix_mask(l2);
    b3 |= prefix_mask(l3);

    float4* __restrict__ op = out + (size_t)(s * SEG_LEN) * row4 + c;
    #pragma unroll
    for (int tb = 0; tb < SEG_LEN; tb += 16) {
        #pragma unroll
        for (int k = 0; k < 16; ++k) {
            const int t = tb + k;
            float4 o;
            o.x = __uint_as_float((unsigned)(-(int)((b0 >> t) & 1ull)) & 0x3F800000u);
            o.y = __uint_as_float((unsigned)(-(int)((b1 >> t) & 1ull)) & 0x3F800000u);
            o.z = __uint_as_float((unsigned)(-(int)((b2 >> t) & 1ull)) & 0x3F800000u);
            o.w = __uint_as_float((unsigned)(-(int)((b3 >> t) & 1ull)) & 0x3F800000u);
            __stcs(&op[(size_t)t * row4], o);
        }
    }
}

// ---- Fallback (odd shapes): halo scan ----
__global__ __launch_bounds__(BLOCK) void psp_scan_kernel(
    const float4* __restrict__ x, float4* __restrict__ out,
    const int* __restrict__ durp, int row4, int T, int seg_len)
{
    const int c = blockIdx.x * BLOCK + threadIdx.x;
    if (c >= row4) return;
    int d = 100;
    if (durp) { int dv = *durp; if (dv > 0 && dv <= T * 16) d = dv; }
    const int t0 = blockIdx.y * seg_len;
    int th = t0 - (d - 1); if (th < 0) th = 0;
    int ax = 1 << 28, ay = 1 << 28, az = 1 << 28, aw = 1 << 28;
    for (int t = th; t < t0; ++t) {
        float4 v = x[(size_t)t * row4 + c];
        ax = (v.x != 0.0f) ? 0 : ax + 1; ay = (v.y != 0.0f) ? 0 : ay + 1;
        az = (v.z != 0.0f) ? 0 : az + 1; aw = (v.w != 0.0f) ? 0 : aw + 1;
    }
    int tend = t0 + seg_len; if (tend > T) tend = T;
    for (int t = t0; t < tend; ++t) {
        float4 v = x[(size_t)t * row4 + c];
        ax = (v.x != 0.0f) ? 0 : ax + 1; ay = (v.y != 0.0f) ? 0 : ay + 1;
        az = (v.z != 0.0f) ? 0 : az + 1; aw = (v.w != 0.0f) ? 0 : aw + 1;
        float4 o;
        o.x = (ax < d) ? 1.0f : 0.0f; o.y = (ay < d) ? 1.0f : 0.0f;
        o.z = (az < d) ? 1.0f : 0.0f; o.w = (aw < d) ? 1.0f : 0.0f;
        out[(size_t)t * row4 + c] = o;
    }
}

extern "C" void kernel_launch(void* const* d_in, const int* in_sizes, int n_in,
                              void* d_out, int out_size)
{
    const float* x = (const float*)d_in[0];
    const int* durp = (n_in > 1) ? (const int*)d_in[1] : nullptr;
    float* out = (float*)d_out;

    const int total = in_sizes[0];
    const int T = TDIM;
    const int row = total / T;
    const int row4 = row / 4;

    if ((row % 4 == 0) && (row4 <= MAXC) && (total == T * row)) {
        const int gx = (row4 + BLOCK - 1) / BLOCK;
        psp_pass1<<<dim3(gx, SEG), BLOCK>>>((const float4*)x, row4);
        psp_pass2<<<dim3(gx, SEG), BLOCK>>>((float4*)out, durp, row4);
    } else {
        const int seg = 8, seg_len = (T + seg - 1) / seg;
        dim3 grid((row4 + BLOCK - 1) / BLOCK, seg);
        psp_scan_kernel<<<grid, BLOCK>>>((const float4*)x, (float4*)out,
                                         durp, row4, T, seg_len);
    }
}

// round 7
// speedup vs baseline: 2.0033x; 1.0010x over previous
#include <cuda_runtime.h>
#include <cuda_bf16.h>
#include <cstdint>

// BinaryTimedPSP: out[t] = clip(causal boxcar sum width d, 0, 1).
// Binary spikes => out[t] = 1 iff any spike in [t-d+1, t].
//
// Two-pass, synchronization-free:
//   P1: x -> per-(segment, component) 64-bit spike masks (256MB read, 8MB write)
//   P2: masks (+ parallel bounded lookback, L2-hot) -> output bits -> stores.
// ALU-lean bit ops: spike floats are exactly 0.0f / 1.0f, so the mask bit is
// extracted straight from float bit 23 (LOP3-fusable), and bit->float uses a
// sign-extend trick on 32-bit halves.

#define TDIM    2048
#define SEG     32
#define SEG_LEN 64
#define BLOCK   256
#define MAXC    8192          // max float4 column-groups (B*N/4)
#define BIGAGE  (1u << 20)

__device__ ulonglong4 g_mask[SEG * MAXC];   // 8 MiB

__device__ __forceinline__ unsigned long long window_or(unsigned long long s, unsigned d) {
    unsigned long long r = s;
    unsigned w = 1;
    while (w < d && w < 64u) {
        unsigned sh = d - w;
        if (sh > w) sh = w;
        r |= r << sh;
        w += sh;
    }
    return r;
}
__device__ __forceinline__ unsigned long long prefix_mask(unsigned len) {
    return (len >= 64u) ? ~0ull : ((1ull << len) - 1ull);
}
__device__ __forceinline__ unsigned load_d(const int* durp) {
    unsigned d = 100;
    if (durp) {
        int dv = *durp;
        if (dv > 0 && dv <= TDIM * 16) d = (unsigned)dv;
    }
    return d;
}

// v is 0x00000000 (0.0f) or 0x3F800000 (1.0f). Move bit 23 to bit t (t in 0..31),
// masked. The & + | accumulate fuses into LOP3; total 2 ops per bit.
__device__ __forceinline__ unsigned spikebit(unsigned v, int t) {
    unsigned sh = (t <= 23) ? (v >> (23 - t)) : (v << (t - 23));
    return sh & (1u << t);
}

// ---- Pass 1: build spike masks ----
__global__ __launch_bounds__(BLOCK) void psp_pass1(
    const uint4* __restrict__ x, int row4)
{
    const int c = blockIdx.x * BLOCK + threadIdx.x;
    if (c >= row4) return;
    const int s = blockIdx.y;
    const uint4* __restrict__ xp = x + (size_t)(s * SEG_LEN) * row4 + c;

    unsigned lo0 = 0, lo1 = 0, lo2 = 0, lo3 = 0;
    unsigned hi0 = 0, hi1 = 0, hi2 = 0, hi3 = 0;
    #pragma unroll
    for (int tb = 0; tb < SEG_LEN; tb += 8) {
        uint4 v[8];
        #pragma unroll
        for (int k = 0; k < 8; ++k)
            v[k] = __ldcs(&xp[(size_t)(tb + k) * row4]);
        #pragma unroll
        for (int k = 0; k < 8; ++k) {
            const int t = tb + k;
            if (t < 32) {
                lo0 |= spikebit(v[k].x, t);
                lo1 |= spikebit(v[k].y, t);
                lo2 |= spikebit(v[k].z, t);
                lo3 |= spikebit(v[k].w, t);
            } else {
                hi0 |= spikebit(v[k].x, t - 32);
                hi1 |= spikebit(v[k].y, t - 32);
                hi2 |= spikebit(v[k].z, t - 32);
                hi3 |= spikebit(v[k].w, t - 32);
            }
        }
    }
    ulonglong4 m;
    m.x = (unsigned long long)lo0 | ((unsigned long long)hi0 << 32);
    m.y = (unsigned long long)lo1 | ((unsigned long long)hi1 << 32);
    m.z = (unsigned long long)lo2 | ((unsigned long long)hi2 << 32);
    m.w = (unsigned long long)lo3 | ((unsigned long long)hi3 << 32);
    g_mask[s * MAXC + c] = m;   // default caching: keep masks in L2 for pass2
}

// ---- Pass 2: parallel bounded lookback + window-OR + streaming stores ----
__global__ __launch_bounds__(BLOCK) void psp_pass2(
    float4* __restrict__ out, const int* __restrict__ durp, int row4)
{
    const int c = blockIdx.x * BLOCK + threadIdx.x;
    if (c >= row4) return;
    const int s = blockIdx.y;
    const unsigned d = load_d(durp);

    // issue all (up to 3) mask loads in parallel: own + 2 predecessors
    ulonglong4 m = g_mask[s * MAXC + c];
    ulonglong4 pm1 = {0, 0, 0, 0}, pm2 = {0, 0, 0, 0};
    if (s >= 1)            pm1 = g_mask[(s - 1) * MAXC + c];
    if (s >= 2 && d > 65u) pm2 = g_mask[(s - 2) * MAXC + c];

    uint4 inc;
    inc.x = pm1.x ? (unsigned)__clzll(pm1.x) : (pm2.x ? 64u + (unsigned)__clzll(pm2.x) : BIGAGE);
    inc.y = pm1.y ? (unsigned)__clzll(pm1.y) : (pm2.y ? 64u + (unsigned)__clzll(pm2.y) : BIGAGE);
    inc.z = pm1.z ? (unsigned)__clzll(pm1.z) : (pm2.z ? 64u + (unsigned)__clzll(pm2.z) : BIGAGE);
    inc.w = pm1.w ? (unsigned)__clzll(pm1.w) : (pm2.w ? 64u + (unsigned)__clzll(pm2.w) : BIGAGE);

    if (d > 129u) {   // rare general case: continue lookback past 2 segments
        unsigned base = 128;
        for (int j = s - 3; j >= 0 && base + 1u < d; --j) {
            if (inc.x != BIGAGE && inc.y != BIGAGE && inc.z != BIGAGE && inc.w != BIGAGE)
                break;
            ulonglong4 pm = g_mask[j * MAXC + c];
            if (inc.x == BIGAGE && pm.x) inc.x = base + (unsigned)__clzll(pm.x);
            if (inc.y == BIGAGE && pm.y) inc.y = base + (unsigned)__clzll(pm.y);
            if (inc.z == BIGAGE && pm.z) inc.z = base + (unsigned)__clzll(pm.z);
            if (inc.w == BIGAGE && pm.w) inc.w = base + (unsigned)__clzll(pm.w);
            base += SEG_LEN;
        }
    }

    unsigned long long b0 = window_or(m.x, d);
    unsigned long long b1 = window_or(m.y, d);
    unsigned long long b2 = window_or(m.z, d);
    unsigned long long b3 = window_or(m.w, d);

    // prefix fix: bits t < min(first_spike, d-1-inc) forced to 1
    unsigned p0 = m.x ? (unsigned)(__ffsll((long long)m.x) - 1) : 64u;
    unsigned p1 = m.y ? (unsigned)(__ffsll((long long)m.y) - 1) : 64u;
    unsigned p2 = m.z ? (unsigned)(__ffsll((long long)m.z) - 1) : 64u;
    unsigned p3 = m.w ? (unsigned)(__ffsll((long long)m.w) - 1) : 64u;
    unsigned l0 = (inc.x + 1u < d) ? min(p0, d - 1u - inc.x) : 0u;
    unsigned l1 = (inc.y + 1u < d) ? min(p1, d - 1u - inc.y) : 0u;
    unsigned l2 = (inc.z + 1u < d) ? min(p2, d - 1u - inc.z) : 0u;
    unsigned l3 = (inc.w + 1u < d) ? min(p3, d - 1u - inc.w) : 0u;
    b0 |= prefix_mask(l0);
    b1 |= prefix_mask(l1);
    b2 |= prefix_mask(l2);
    b3 |= prefix_mask(l3);

    // split into 32-bit halves; 3 fixed-lat ops per component (no funnel shifts)
    const unsigned a0 = (unsigned)b0, A0 = (unsigned)(b0 >> 32);
    const unsigned a1 = (unsigned)b1, A1 = (unsigned)(b1 >> 32);
    const unsigned a2 = (unsigned)b2, A2 = (unsigned)(b2 >> 32);
    const unsigned a3 = (unsigned)b3, A3 = (unsigned)(b3 >> 32);

    float4* __restrict__ op = out + (size_t)(s * SEG_LEN) * row4 + c;
    #pragma unroll
    for (int t = 0; t < 32; ++t) {
        float4 o;
        o.x = __uint_as_float((unsigned)(((int)(a0 << (31 - t))) >> 31) & 0x3F800000u);
        o.y = __uint_as_float((unsigned)(((int)(a1 << (31 - t))) >> 31) & 0x3F800000u);
        o.z = __uint_as_float((unsigned)(((int)(a2 << (31 - t))) >> 31) & 0x3F800000u);
        o.w = __uint_as_float((unsigned)(((int)(a3 << (31 - t))) >> 31) & 0x3F800000u);
        __stcs(&op[(size_t)t * row4], o);
    }
    #pragma unroll
    for (int t = 0; t < 32; ++t) {
        float4 o;
        o.x = __uint_as_float((unsigned)(((int)(A0 << (31 - t))) >> 31) & 0x3F800000u);
        o.y = __uint_as_float((unsigned)(((int)(A1 << (31 - t))) >> 31) & 0x3F800000u);
        o.z = __uint_as_float((unsigned)(((int)(A2 << (31 - t))) >> 31) & 0x3F800000u);
        o.w = __uint_as_float((unsigned)(((int)(A3 << (31 - t))) >> 31) & 0x3F800000u);
        __stcs(&op[(size_t)(t + 32) * row4], o);
    }
}

// ---- Fallback (odd shapes): halo scan ----
__global__ __launch_bounds__(128) void psp_scan_kernel(
    const float4* __restrict__ x, float4* __restrict__ out,
    const int* __restrict__ durp, int row4, int T, int seg_len)
{
    const int c = blockIdx.x * 128 + threadIdx.x;
    if (c >= row4) return;
    int d = 100;
    if (durp) { int dv = *durp; if (dv > 0 && dv <= T * 16) d = dv; }
    const int t0 = blockIdx.y * seg_len;
    int th = t0 - (d - 1); if (th < 0) th = 0;
    int ax = 1 << 28, ay = 1 << 28, az = 1 << 28, aw = 1 << 28;
    for (int t = th; t < t0; ++t) {
        float4 v = x[(size_t)t * row4 + c];
        ax = (v.x != 0.0f) ? 0 : ax + 1; ay = (v.y != 0.0f) ? 0 : ay + 1;
        az = (v.z != 0.0f) ? 0 : az + 1; aw = (v.w != 0.0f) ? 0 : aw + 1;
    }
    int tend = t0 + seg_len; if (tend > T) tend = T;
    for (int t = t0; t < tend; ++t) {
        float4 v = x[(size_t)t * row4 + c];
        ax = (v.x != 0.0f) ? 0 : ax + 1; ay = (v.y != 0.0f) ? 0 : ay + 1;
        az = (v.z != 0.0f) ? 0 : az + 1; aw = (v.w != 0.0f) ? 0 : aw + 1;
        float4 o;
        o.x = (ax < d) ? 1.0f : 0.0f; o.y = (ay < d) ? 1.0f : 0.0f;
        o.z = (az < d) ? 1.0f : 0.0f; o.w = (aw < d) ? 1.0f : 0.0f;
        out[(size_t)t * row4 + c] = o;
    }
}

extern "C" void kernel_launch(void* const* d_in, const int* in_sizes, int n_in,
                              void* d_out, int out_size)
{
    const float* x = (const float*)d_in[0];
    const int* durp = (n_in > 1) ? (const int*)d_in[1] : nullptr;
    float* out = (float*)d_out;

    const int total = in_sizes[0];
    const int T = TDIM;
    const int row = total / T;
    const int row4 = row / 4;

    if ((row % 4 == 0) && (row4 <= MAXC) && (total == T * row)) {
        const int gx = (row4 + BLOCK - 1) / BLOCK;
        psp_pass1<<<dim3(gx, SEG), BLOCK>>>((const uint4*)x, row4);
        psp_pass2<<<dim3(gx, SEG), BLOCK>>>((float4*)out, durp, row4);
    } else {
        const int seg = 8, seg_len = (T + seg - 1) / seg;
        dim3 grid((row4 + 127) / 128, seg);
        psp_scan_kernel<<<grid, 128>>>((const float4*)x, (float4*)out,
                                       durp, row4, T, seg_len);
    }
}

// round 8
// speedup vs baseline: 2.0938x; 1.0452x over previous
#include <cuda_runtime.h>
#include <cuda_bf16.h>
#include <cstdint>

// BinaryTimedPSP: out[t] = clip(causal boxcar sum width d, 0, 1).
// Binary spikes => out[t] = 1 iff any spike in [t-d+1, t].
//
// Two-pass, synchronization-free, PDL-overlapped:
//   P1: x -> per-(segment, component) 64-bit spike masks (256MB read, 8MB write)
//       8 back-to-back LDG.128 forced via asm volatile (real MLP=8).
//   P2: masks (+ parallel bounded lookback, L2-hot) -> output bits -> stores.
//       Launched with programmatic stream serialization; prologue overlaps P1.

#define TDIM    2048
#define SEG     32
#define SEG_LEN 64
#define BLOCK1  128
#define BLOCK2  256
#define MAXC    8192          // max float4 column-groups (B*N/4)
#define BIGAGE  (1u << 20)

__device__ ulonglong4 g_mask[SEG * MAXC];   // 8 MiB

__device__ __forceinline__ unsigned long long window_or(unsigned long long s, unsigned d) {
    unsigned long long r = s;
    unsigned w = 1;
    while (w < d && w < 64u) {
        unsigned sh = d - w;
        if (sh > w) sh = w;
        r |= r << sh;
        w += sh;
    }
    return r;
}
__device__ __forceinline__ unsigned long long prefix_mask(unsigned len) {
    return (len >= 64u) ? ~0ull : ((1ull << len) - 1ull);
}
__device__ __forceinline__ unsigned load_d(const int* durp) {
    unsigned d = 100;
    if (durp) {
        int dv = *durp;
        if (dv > 0 && dv <= TDIM * 16) d = (unsigned)dv;
    }
    return d;
}

// v is 0x00000000 (0.0f) or 0x3F800000 (1.0f). Move bit 23 to bit t, masked.
__device__ __forceinline__ unsigned spikebit(unsigned v, int t) {
    unsigned sh = (t <= 23) ? (v >> (23 - t)) : (v << (t - 23));
    return sh & (1u << t);
}

__device__ __forceinline__ void ldg128_cs(const uint4* p,
                                          unsigned& a, unsigned& b,
                                          unsigned& c, unsigned& d) {
    asm volatile("ld.global.cs.v4.u32 {%0,%1,%2,%3}, [%4];"
                 : "=r"(a), "=r"(b), "=r"(c), "=r"(d) : "l"(p));
}

// ---- Pass 1: build spike masks (forced 8-deep load batches) ----
__global__ __launch_bounds__(BLOCK1) void psp_pass1(
    const uint4* __restrict__ x, int row4)
{
    const int c = blockIdx.x * BLOCK1 + threadIdx.x;
    const int s = blockIdx.y;
    if (c < row4) {
        const uint4* __restrict__ xp = x + (size_t)(s * SEG_LEN) * row4 + c;

        unsigned lo0 = 0, lo1 = 0, lo2 = 0, lo3 = 0;
        unsigned hi0 = 0, hi1 = 0, hi2 = 0, hi3 = 0;
        #pragma unroll
        for (int tb = 0; tb < SEG_LEN; tb += 8) {
            unsigned v[8][4];
            // 8 consecutive volatile loads: ptxas cannot sink/serialize them.
            #pragma unroll
            for (int k = 0; k < 8; ++k)
                ldg128_cs(&xp[(size_t)(tb + k) * row4],
                          v[k][0], v[k][1], v[k][2], v[k][3]);
            #pragma unroll
            for (int k = 0; k < 8; ++k) {
                const int t = tb + k;
                if (t < 32) {
                    lo0 |= spikebit(v[k][0], t);
                    lo1 |= spikebit(v[k][1], t);
                    lo2 |= spikebit(v[k][2], t);
                    lo3 |= spikebit(v[k][3], t);
                } else {
                    hi0 |= spikebit(v[k][0], t - 32);
                    hi1 |= spikebit(v[k][1], t - 32);
                    hi2 |= spikebit(v[k][2], t - 32);
                    hi3 |= spikebit(v[k][3], t - 32);
                }
            }
        }
        ulonglong4 m;
        m.x = (unsigned long long)lo0 | ((unsigned long long)hi0 << 32);
        m.y = (unsigned long long)lo1 | ((unsigned long long)hi1 << 32);
        m.z = (unsigned long long)lo2 | ((unsigned long long)hi2 << 32);
        m.w = (unsigned long long)lo3 | ((unsigned long long)hi3 << 32);
        g_mask[s * MAXC + c] = m;
    }
    // make mask stores visible, then let the dependent grid proceed
    __threadfence();
    cudaTriggerProgrammaticLaunchCompletion();
}

// ---- Pass 2: parallel bounded lookback + window-OR + streaming stores ----
__global__ __launch_bounds__(BLOCK2) void psp_pass2(
    float4* __restrict__ out, const int* __restrict__ durp, int row4)
{
    const int c = blockIdx.x * BLOCK2 + threadIdx.x;
    const int s = blockIdx.y;
    // prologue overlapped with pass1 (durp is harness input, stable pre-graph)
    const unsigned d = load_d(durp);
    float4* __restrict__ op = out + (size_t)(s * SEG_LEN) * row4 + c;

    cudaGridDependencySynchronize();
    if (c >= row4) return;

    // issue all (up to 3) mask loads in parallel: own + 2 predecessors
    ulonglong4 m = g_mask[s * MAXC + c];
    ulonglong4 pm1 = {0, 0, 0, 0}, pm2 = {0, 0, 0, 0};
    if (s >= 1)            pm1 = g_mask[(s - 1) * MAXC + c];
    if (s >= 2 && d > 65u) pm2 = g_mask[(s - 2) * MAXC + c];

    uint4 inc;
    inc.x = pm1.x ? (unsigned)__clzll(pm1.x) : (pm2.x ? 64u + (unsigned)__clzll(pm2.x) : BIGAGE);
    inc.y = pm1.y ? (unsigned)__clzll(pm1.y) : (pm2.y ? 64u + (unsigned)__clzll(pm2.y) : BIGAGE);
    inc.z = pm1.z ? (unsigned)__clzll(pm1.z) : (pm2.z ? 64u + (unsigned)__clzll(pm2.z) : BIGAGE);
    inc.w = pm1.w ? (unsigned)__clzll(pm1.w) : (pm2.w ? 64u + (unsigned)__clzll(pm2.w) : BIGAGE);

    if (d > 129u) {   // rare general case: continue lookback past 2 segments
        unsigned base = 128;
        for (int j = s - 3; j >= 0 && base + 1u < d; --j) {
            if (inc.x != BIGAGE && inc.y != BIGAGE && inc.z != BIGAGE && inc.w != BIGAGE)
                break;
            ulonglong4 pm = g_mask[j * MAXC + c];
            if (inc.x == BIGAGE && pm.x) inc.x = base + (unsigned)__clzll(pm.x);
            if (inc.y == BIGAGE && pm.y) inc.y = base + (unsigned)__clzll(pm.y);
            if (inc.z == BIGAGE && pm.z) inc.z = base + (unsigned)__clzll(pm.z);
            if (inc.w == BIGAGE && pm.w) inc.w = base + (unsigned)__clzll(pm.w);
            base += SEG_LEN;
        }
    }

    unsigned long long b0 = window_or(m.x, d);
    unsigned long long b1 = window_or(m.y, d);
    unsigned long long b2 = window_or(m.z, d);
    unsigned long long b3 = window_or(m.w, d);

    // prefix fix: bits t < min(first_spike, d-1-inc) forced to 1
    unsigned p0 = m.x ? (unsigned)(__ffsll((long long)m.x) - 1) : 64u;
    unsigned p1 = m.y ? (unsigned)(__ffsll((long long)m.y) - 1) : 64u;
    unsigned p2 = m.z ? (unsigned)(__ffsll((long long)m.z) - 1) : 64u;
    unsigned p3 = m.w ? (unsigned)(__ffsll((long long)m.w) - 1) : 64u;
    unsigned l0 = (inc.x + 1u < d) ? min(p0, d - 1u - inc.x) : 0u;
    unsigned l1 = (inc.y + 1u < d) ? min(p1, d - 1u - inc.y) : 0u;
    unsigned l2 = (inc.z + 1u < d) ? min(p2, d - 1u - inc.z) : 0u;
    unsigned l3 = (inc.w + 1u < d) ? min(p3, d - 1u - inc.w) : 0u;
    b0 |= prefix_mask(l0);
    b1 |= prefix_mask(l1);
    b2 |= prefix_mask(l2);
    b3 |= prefix_mask(l3);

    const unsigned a0 = (unsigned)b0, A0 = (unsigned)(b0 >> 32);
    const unsigned a1 = (unsigned)b1, A1 = (unsigned)(b1 >> 32);
    const unsigned a2 = (unsigned)b2, A2 = (unsigned)(b2 >> 32);
    const unsigned a3 = (unsigned)b3, A3 = (unsigned)(b3 >> 32);

    #pragma unroll
    for (int t = 0; t < 32; ++t) {
        float4 o;
        o.x = __uint_as_float((unsigned)(((int)(a0 << (31 - t))) >> 31) & 0x3F800000u);
        o.y = __uint_as_float((unsigned)(((int)(a1 << (31 - t))) >> 31) & 0x3F800000u);
        o.z = __uint_as_float((unsigned)(((int)(a2 << (31 - t))) >> 31) & 0x3F800000u);
        o.w = __uint_as_float((unsigned)(((int)(a3 << (31 - t))) >> 31) & 0x3F800000u);
        __stcs(&op[(size_t)t * row4], o);
    }
    #pragma unroll
    for (int t = 0; t < 32; ++t) {
        float4 o;
        o.x = __uint_as_float((unsigned)(((int)(A0 << (31 - t))) >> 31) & 0x3F800000u);
        o.y = __uint_as_float((unsigned)(((int)(A1 << (31 - t))) >> 31) & 0x3F800000u);
        o.z = __uint_as_float((unsigned)(((int)(A2 << (31 - t))) >> 31) & 0x3F800000u);
        o.w = __uint_as_float((unsigned)(((int)(A3 << (31 - t))) >> 31) & 0x3F800000u);
        __stcs(&op[(size_t)(t + 32) * row4], o);
    }
}

// ---- Fallback (odd shapes): halo scan ----
__global__ __launch_bounds__(128) void psp_scan_kernel(
    const float4* __restrict__ x, float4* __restrict__ out,
    const int* __restrict__ durp, int row4, int T, int seg_len)
{
    const int c = blockIdx.x * 128 + threadIdx.x;
    if (c >= row4) return;
    int d = 100;
    if (durp) { int dv = *durp; if (dv > 0 && dv <= T * 16) d = dv; }
    const int t0 = blockIdx.y * seg_len;
    int th = t0 - (d - 1); if (th < 0) th = 0;
    int ax = 1 << 28, ay = 1 << 28, az = 1 << 28, aw = 1 << 28;
    for (int t = th; t < t0; ++t) {
        float4 v = x[(size_t)t * row4 + c];
        ax = (v.x != 0.0f) ? 0 : ax + 1; ay = (v.y != 0.0f) ? 0 : ay + 1;
        az = (v.z != 0.0f) ? 0 : az + 1; aw = (v.w != 0.0f) ? 0 : aw + 1;
    }
    int tend = t0 + seg_len; if (tend > T) tend = T;
    for (int t = t0; t < tend; ++t) {
        float4 v = x[(size_t)t * row4 + c];
        ax = (v.x != 0.0f) ? 0 : ax + 1; ay = (v.y != 0.0f) ? 0 : ay + 1;
        az = (v.z != 0.0f) ? 0 : az + 1; aw = (v.w != 0.0f) ? 0 : aw + 1;
        float4 o;
        o.x = (ax < d) ? 1.0f : 0.0f; o.y = (ay < d) ? 1.0f : 0.0f;
        o.z = (az < d) ? 1.0f : 0.0f; o.w = (aw < d) ? 1.0f : 0.0f;
        out[(size_t)t * row4 + c] = o;
    }
}

extern "C" void kernel_launch(void* const* d_in, const int* in_sizes, int n_in,
                              void* d_out, int out_size)
{
    const float* x = (const float*)d_in[0];
    const int* durp = (n_in > 1) ? (const int*)d_in[1] : nullptr;
    float* out = (float*)d_out;

    const int total = in_sizes[0];
    const int T = TDIM;
    const int row = total / T;
    const int row4 = row / 4;

    if ((row % 4 == 0) && (row4 <= MAXC) && (total == T * row)) {
        const int gx1 = (row4 + BLOCK1 - 1) / BLOCK1;
        psp_pass1<<<dim3(gx1, SEG), BLOCK1>>>((const uint4*)x, row4);

        // pass2 with programmatic dependent launch (overlap ramp with pass1 tail)
        cudaLaunchConfig_t cfg = {};
        cfg.gridDim  = dim3((row4 + BLOCK2 - 1) / BLOCK2, SEG, 1);
        cfg.blockDim = dim3(BLOCK2, 1, 1);
        cfg.dynamicSmemBytes = 0;
        cfg.stream = 0;
        cudaLaunchAttribute attr[1];
        attr[0].id = cudaLaunchAttributeProgrammaticStreamSerialization;
        attr[0].val.programmaticStreamSerializationAllowed = 1;
        cfg.attrs = attr;
        cfg.numAttrs = 1;
        cudaError_t e = cudaLaunchKernelEx(&cfg, psp_pass2,
                                           (float4*)out, (const int*)durp, row4);
        if (e != cudaSuccess) {   // PDL unavailable: plain launch
            psp_pass2<<<cfg.gridDim, cfg.blockDim>>>((float4*)out, durp, row4);
        }
    } else {
        const int seg = 8, seg_len = (T + seg - 1) / seg;
        dim3 grid((row4 + 127) / 128, seg);
        psp_scan_kernel<<<grid, 128>>>((const float4*)x, (float4*)out,
                                       durp, row4, T, seg_len);
    }
}